// round 2
// baseline (speedup 1.0000x reference)
#include <cuda_runtime.h>
#include <math.h>

// ---------------------------------------------------------------------------
// MoE layer: shared SwiGLU expert + top-2-of-8 routed SwiGLU experts.
// n = 4096 tokens, D = H = 1024.
//
// Pipeline (all deterministic, graph-capturable, allocation-free):
//   0. rconst : loop_emb @ Wr[1024:] -> 8 router bias constants
//   1. router : per-token logits -> sigmoid -> stable top-2 -> (expert, weight)
//               per slot s = 2n+k
//   2. dispatch: per-expert ordered slot lists via block-wide prefix scan
//   3. gate/up GEMMs (routed gathered + shared identity) -> gbuf/ubuf
//   4. h = silu(g)*u
//   5. down GEMMs (routed gathered + shared) -> ybuf (scaled by routing weight)
//   6. out[n] = ybuf[shared(n)] + ybuf[2n] + ybuf[2n+1]
// ---------------------------------------------------------------------------

#define DIMD   1024
#define DIMH   1024
#define NTOK   4096
#define NEXP   8
#define CAP    4096            // max tokens per expert
#define SLOTS  (NTOK * 2)      // 8192 routed (token, k) slots
#define TOT    (SLOTS + NTOK)  // + 4096 shared rows

// scratch (static device memory is the sanctioned workaround for no-alloc rule)
__device__ float g_gbuf[(size_t)TOT * DIMH];
__device__ float g_ubuf[(size_t)TOT * DIMH];
__device__ float g_hbuf[(size_t)TOT * DIMH];
__device__ float g_ybuf[(size_t)TOT * DIMD];
__device__ int   g_list[NEXP * CAP];
__device__ int   g_count[NEXP];
__device__ int   g_expert_of[SLOTS];
__device__ float g_wslot[SLOTS];
__device__ float g_rconst[NEXP];

// ---------------------------------------------------------------------------
// 0. router bias constants: rconst[e] = sum_d loop_emb[d] * Wr[1024+d][e]
// ---------------------------------------------------------------------------
__global__ void rconst_kernel(const float* __restrict__ Wr,
                              const float* __restrict__ loop_table,
                              const int* __restrict__ loop_idx) {
    __shared__ float red[256][NEXP];
    int li = loop_idx[0];
    float acc[NEXP];
#pragma unroll
    for (int e = 0; e < NEXP; e++) acc[e] = 0.f;
    for (int d = threadIdx.x; d < DIMD; d += 256) {
        float lv = loop_table[(size_t)li * DIMD + d];
        const float* wr = Wr + (size_t)(DIMD + d) * NEXP;
#pragma unroll
        for (int e = 0; e < NEXP; e++) acc[e] += lv * wr[e];
    }
#pragma unroll
    for (int e = 0; e < NEXP; e++) red[threadIdx.x][e] = acc[e];
    __syncthreads();
    if (threadIdx.x < NEXP) {
        float s = 0.f;
        for (int i = 0; i < 256; i++) s += red[i][threadIdx.x];  // fixed order
        g_rconst[threadIdx.x] = s;
    }
}

// ---------------------------------------------------------------------------
// 1. router: one warp per token
// ---------------------------------------------------------------------------
__global__ void router_kernel(const float* __restrict__ x,
                              const float* __restrict__ Wr) {
    int warp = threadIdx.x >> 5, lane = threadIdx.x & 31;
    int n = blockIdx.x * 8 + warp;
    if (n >= NTOK) return;
    const float* xr = x + (size_t)n * DIMD;
    float acc[NEXP];
#pragma unroll
    for (int e = 0; e < NEXP; e++) acc[e] = 0.f;
    for (int d = lane; d < DIMD; d += 32) {
        float xv = xr[d];
        const float* wr = Wr + (size_t)d * NEXP;
#pragma unroll
        for (int e = 0; e < NEXP; e++) acc[e] += xv * wr[e];
    }
#pragma unroll
    for (int e = 0; e < NEXP; e++)
#pragma unroll
        for (int off = 16; off > 0; off >>= 1)
            acc[e] += __shfl_down_sync(0xffffffffu, acc[e], off);
    if (lane == 0) {
        float p[NEXP];
#pragma unroll
        for (int e = 0; e < NEXP; e++)
            p[e] = 1.f / (1.f + expf(-(acc[e] + g_rconst[e])));
        // stable top-2 (strict >, lowest index wins ties — matches lax.top_k)
        float b1 = -1.f; int i1 = 0;
#pragma unroll
        for (int e = 0; e < NEXP; e++) if (p[e] > b1) { b1 = p[e]; i1 = e; }
        float b2 = -1.f; int i2 = 0;
#pragma unroll
        for (int e = 0; e < NEXP; e++)
            if (e != i1 && p[e] > b2) { b2 = p[e]; i2 = e; }
        g_expert_of[2 * n]     = i1;  g_wslot[2 * n]     = b1;
        g_expert_of[2 * n + 1] = i2;  g_wslot[2 * n + 1] = b2;
    }
}

// ---------------------------------------------------------------------------
// 2. dispatch: block e builds ordered list of slots routed to expert e
// ---------------------------------------------------------------------------
__global__ void dispatch_kernel() {
    int e = blockIdx.x;
    __shared__ int warp_tot[8];
    __shared__ int warp_off[8];
    __shared__ int s_base;
    if (threadIdx.x == 0) s_base = 0;
    __syncthreads();
    int lane = threadIdx.x & 31, w = threadIdx.x >> 5;
    for (int s0 = 0; s0 < SLOTS; s0 += 256) {
        int s = s0 + threadIdx.x;
        bool f = (g_expert_of[s] == e);
        unsigned bal = __ballot_sync(0xffffffffu, f);
        if (lane == 0) warp_tot[w] = __popc(bal);
        __syncthreads();
        if (threadIdx.x == 0) {
            int a = s_base;
            for (int i = 0; i < 8; i++) { warp_off[i] = a; a += warp_tot[i]; }
            s_base = a;
        }
        __syncthreads();
        if (f) {
            int pos = warp_off[w] + __popc(bal & ((1u << lane) - 1u));
            g_list[e * CAP + pos] = s;
        }
        __syncthreads();
    }
    if (threadIdx.x == 0) g_count[e] = s_base;
}

// ---------------------------------------------------------------------------
// Tiled fp32 GEMM, 128x128x8, 256 threads, 8x8 per thread, reg prefetch.
// C[slot] = (A[arow] @ B_e) * w    where rows come from an expert list or
// an identity range. K = N = 1024 always.
//   row_shift=1: A row = token (slot>>1 via list, or r for identity)  [x input]
//   row_shift=0: A row = slot                                        [hbuf]
// ---------------------------------------------------------------------------
__global__ __launch_bounds__(256)
void gemm_kernel(const float* __restrict__ A,
                 const float* __restrict__ Bbase, size_t bstride,
                 float* __restrict__ C,
                 const int* __restrict__ list,
                 const int* __restrict__ counts, int fixed_count,
                 int row_shift, int slot_base,
                 const float* __restrict__ wslot) {
    int e = blockIdx.z;
    int cnt = list ? counts[e] : fixed_count;
    int m0 = blockIdx.y * 128;
    if (m0 >= cnt) return;
    int n0 = blockIdx.x * 128;
    const float* B = Bbase + (size_t)e * bstride;

    __shared__ float As[8][128];
    __shared__ float Bs[8][128];

    int tid = threadIdx.x;
    // A loader: one float4 per thread per k-step
    int lr  = m0 + (tid >> 1);
    int lk4 = (tid & 1) * 4;
    int lrow = tid >> 1;
    const float* aptr = A;
    bool avalid = false;
    if (lr < cnt) {
        int slot = list ? list[e * CAP + lr] : (slot_base + lr);
        int arow = row_shift ? (list ? (slot >> 1) : lr) : slot;
        aptr = A + (size_t)arow * 1024 + lk4;
        avalid = true;
    }
    // B loader: one float4 per thread per k-step
    int brow = tid >> 5;
    int bcol = (tid & 31) * 4;
    const float* bptr = B + (size_t)brow * 1024 + n0 + bcol;

    float acc[8][8];
#pragma unroll
    for (int i = 0; i < 8; i++)
#pragma unroll
        for (int j = 0; j < 8; j++) acc[i][j] = 0.f;

    int ty = tid >> 4, tx = tid & 15;
    float4 zero4 = make_float4(0.f, 0.f, 0.f, 0.f);
    float4 av = avalid ? *(const float4*)(aptr) : zero4;
    float4 bv = *(const float4*)(bptr);

#pragma unroll 1
    for (int k0 = 0; k0 < 1024; k0 += 8) {
        As[lk4 + 0][lrow] = av.x;
        As[lk4 + 1][lrow] = av.y;
        As[lk4 + 2][lrow] = av.z;
        As[lk4 + 3][lrow] = av.w;
        *(float4*)&Bs[brow][bcol] = bv;
        __syncthreads();

        float4 av_n = zero4, bv_n = zero4;
        if (k0 + 8 < 1024) {
            av_n = avalid ? *(const float4*)(aptr + k0 + 8) : zero4;
            bv_n = *(const float4*)(bptr + (size_t)(k0 + 8) * 1024);
        }

#pragma unroll
        for (int kk = 0; kk < 8; kk++) {
            float4 a0 = *(float4*)&As[kk][ty * 8];
            float4 a1 = *(float4*)&As[kk][ty * 8 + 4];
            float4 b0 = *(float4*)&Bs[kk][tx * 8];
            float4 b1 = *(float4*)&Bs[kk][tx * 8 + 4];
            float ar[8] = {a0.x, a0.y, a0.z, a0.w, a1.x, a1.y, a1.z, a1.w};
            float br[8] = {b0.x, b0.y, b0.z, b0.w, b1.x, b1.y, b1.z, b1.w};
#pragma unroll
            for (int i = 0; i < 8; i++)
#pragma unroll
                for (int j = 0; j < 8; j++)
                    acc[i][j] += ar[i] * br[j];
        }
        __syncthreads();
        av = av_n; bv = bv_n;
    }

    // epilogue
#pragma unroll
    for (int i = 0; i < 8; i++) {
        int r = m0 + ty * 8 + i;
        if (r >= cnt) continue;
        int slot = list ? list[e * CAP + r] : (slot_base + r);
        float w = wslot ? wslot[slot] : 1.f;
        float* crow = C + (size_t)slot * 1024 + n0 + tx * 8;
        float4 c0 = make_float4(acc[i][0] * w, acc[i][1] * w,
                                acc[i][2] * w, acc[i][3] * w);
        float4 c1 = make_float4(acc[i][4] * w, acc[i][5] * w,
                                acc[i][6] * w, acc[i][7] * w);
        *(float4*)(crow)     = c0;
        *(float4*)(crow + 4) = c1;
    }
}

// ---------------------------------------------------------------------------
// 4. h = silu(g) * u   (all TOT*H elements are written before this runs)
// ---------------------------------------------------------------------------
__global__ void silumul_kernel() {
    size_t i = (size_t)blockIdx.x * 256 + threadIdx.x;  // float4 index
    float4 g = ((const float4*)g_gbuf)[i];
    float4 u = ((const float4*)g_ubuf)[i];
    float4 h;
    h.x = g.x / (1.f + expf(-g.x)) * u.x;
    h.y = g.y / (1.f + expf(-g.y)) * u.y;
    h.z = g.z / (1.f + expf(-g.z)) * u.z;
    h.w = g.w / (1.f + expf(-g.w)) * u.w;
    ((float4*)g_hbuf)[i] = h;
}

// ---------------------------------------------------------------------------
// 6. out[n] = shared[n] + routed_slot0[n] + routed_slot1[n]
// ---------------------------------------------------------------------------
__global__ void final_kernel(float* __restrict__ out) {
    size_t i = (size_t)blockIdx.x * 256 + threadIdx.x;  // float4 index
    size_t n = i / (DIMD / 4);
    size_t c = i % (DIMD / 4);
    const float4* ysh = (const float4*)(g_ybuf + (size_t)(SLOTS + n) * DIMD);
    const float4* y0  = (const float4*)(g_ybuf + (size_t)(2 * n) * DIMD);
    const float4* y1  = (const float4*)(g_ybuf + (size_t)(2 * n + 1) * DIMD);
    float4 a = ysh[c], b = y0[c], d = y1[c];
    float4 o = make_float4(a.x + b.x + d.x, a.y + b.y + d.y,
                           a.z + b.z + d.z, a.w + b.w + d.w);
    ((float4*)out)[i] = o;
}

// ---------------------------------------------------------------------------
extern "C" void kernel_launch(void* const* d_in, const int* in_sizes, int n_in,
                              void* d_out, int out_size) {
    const float* x  = (const float*)d_in[0];
    const float* sg = (const float*)d_in[1];
    const float* su = (const float*)d_in[2];
    const float* sd = (const float*)d_in[3];
    const float* Wg = (const float*)d_in[4];
    const float* Wu = (const float*)d_in[5];
    const float* Wd = (const float*)d_in[6];
    const float* Wr = (const float*)d_in[7];
    const float* lt = (const float*)d_in[8];
    const int*   li = (const int*)d_in[9];
    float* out = (float*)d_out;

    float *gbuf, *ubuf, *hbuf, *ybuf, *ws;
    int *list, *count;
    cudaGetSymbolAddress((void**)&gbuf,  g_gbuf);
    cudaGetSymbolAddress((void**)&ubuf,  g_ubuf);
    cudaGetSymbolAddress((void**)&hbuf,  g_hbuf);
    cudaGetSymbolAddress((void**)&ybuf,  g_ybuf);
    cudaGetSymbolAddress((void**)&list,  g_list);
    cudaGetSymbolAddress((void**)&count, g_count);
    cudaGetSymbolAddress((void**)&ws,    g_wslot);

    rconst_kernel<<<1, 256>>>(Wr, lt, li);
    router_kernel<<<NTOK / 8, 256>>>(x, Wr);
    dispatch_kernel<<<NEXP, 256>>>();

    dim3 gr(8, 32, NEXP);  // routed: N-tiles, M-tiles over CAP, experts
    dim3 gs(8, 32, 1);     // shared: fixed 4096 rows

    size_t wstride = (size_t)DIMD * DIMH;

    // gate
    gemm_kernel<<<gr, 256>>>(x, Wg, wstride, gbuf, list, count, 0, 1, 0, nullptr);
    gemm_kernel<<<gs, 256>>>(x, sg, 0,       gbuf, nullptr, nullptr, NTOK, 1, SLOTS, nullptr);
    // up
    gemm_kernel<<<gr, 256>>>(x, Wu, wstride, ubuf, list, count, 0, 1, 0, nullptr);
    gemm_kernel<<<gs, 256>>>(x, su, 0,       ubuf, nullptr, nullptr, NTOK, 1, SLOTS, nullptr);
    // h = silu(g)*u
    silumul_kernel<<<(TOT * DIMH / 4) / 256, 256>>>();
    // down (routed scaled by routing weight)
    gemm_kernel<<<gr, 256>>>(hbuf, Wd, wstride, ybuf, list, count, 0, 0, 0, ws);
    gemm_kernel<<<gs, 256>>>(hbuf, sd, 0,       ybuf, nullptr, nullptr, NTOK, 0, SLOTS, nullptr);
    // combine
    final_kernel<<<(NTOK * DIMD / 4) / 256, 256>>>(out);
}

// round 4
// speedup vs baseline: 2.8198x; 2.8198x over previous
#include <cuda_runtime.h>
#include <cuda_bf16.h>
#include <cstdint>
#include <math.h>

// ===========================================================================
// MoE layer via mma.sync (HMMA) — tcgen05 is unavailable because the harness
// ptxas targets sm_103 (non-'a'); mma.sync.m16n8k16.bf16 is a baseline
// sm_80+ feature and compiles on compute_103.
// GEMMs run as bf16-split 3-MMA (hi/lo) with fp32 accum -> ~1e-5 rel err.
// ===========================================================================

#define DIMD   1024
#define NTOK   4096
#define NEXP   8
#define CAP    8192
#define SLOTS  (NTOK * 2)
#define TOT    (SLOTS + NTOK)

// ---------------- static scratch ----------------
__device__ float g_gbuf[(size_t)TOT * 1024];
__device__ float g_ubuf[(size_t)TOT * 1024];
__device__ float g_ybuf[(size_t)TOT * 1024];
__device__ __nv_bfloat16 g_Xhi[(size_t)NTOK * 1024];
__device__ __nv_bfloat16 g_Xlo[(size_t)NTOK * 1024];
__device__ __nv_bfloat16 g_Hhi[(size_t)TOT * 1024];
__device__ __nv_bfloat16 g_Hlo[(size_t)TOT * 1024];
// transposed ([out][in] = [n][k]) split weights
__device__ __nv_bfloat16 g_WgThi[(size_t)NEXP << 20];
__device__ __nv_bfloat16 g_WgTlo[(size_t)NEXP << 20];
__device__ __nv_bfloat16 g_WuThi[(size_t)NEXP << 20];
__device__ __nv_bfloat16 g_WuTlo[(size_t)NEXP << 20];
__device__ __nv_bfloat16 g_WdThi[(size_t)NEXP << 20];
__device__ __nv_bfloat16 g_WdTlo[(size_t)NEXP << 20];
__device__ __nv_bfloat16 g_sgThi[1 << 20];
__device__ __nv_bfloat16 g_sgTlo[1 << 20];
__device__ __nv_bfloat16 g_suThi[1 << 20];
__device__ __nv_bfloat16 g_suTlo[1 << 20];
__device__ __nv_bfloat16 g_sdThi[1 << 20];
__device__ __nv_bfloat16 g_sdTlo[1 << 20];
__device__ int   g_list[NEXP * CAP];
__device__ int   g_count[NEXP];
__device__ int   g_expert_of[SLOTS];
__device__ float g_wslot[SLOTS];
__device__ float g_rconst[NEXP];

// ---------------- helpers ----------------
__device__ __forceinline__ uint32_t smem_u32(const void* p) {
    uint32_t a;
    asm("{ .reg .u64 t; cvta.to.shared.u64 t, %1; cvt.u32.u64 %0, t; }"
        : "=r"(a) : "l"(p));
    return a;
}
__device__ __forceinline__ void cp16(uint32_t dst, const void* src) {
    asm volatile("cp.async.cg.shared.global [%0], [%1], 16;" :: "r"(dst), "l"(src));
}
__device__ __forceinline__ void cp_commit() {
    asm volatile("cp.async.commit_group;" ::: "memory");
}
#define CP_WAIT(n) asm volatile("cp.async.wait_group %0;" :: "n"(n) : "memory")

__device__ __forceinline__ void ldsm4(uint32_t* r, uint32_t addr) {
    asm volatile("ldmatrix.sync.aligned.m8n8.x4.shared.b16 {%0,%1,%2,%3}, [%4];"
        : "=r"(r[0]), "=r"(r[1]), "=r"(r[2]), "=r"(r[3]) : "r"(addr));
}
__device__ __forceinline__ void mma16816(float* c, const uint32_t* a,
                                         uint32_t b0, uint32_t b1) {
    asm volatile(
        "mma.sync.aligned.m16n8k16.row.col.f32.bf16.bf16.f32 "
        "{%0,%1,%2,%3}, {%4,%5,%6,%7}, {%8,%9}, {%0,%1,%2,%3};"
        : "+f"(c[0]), "+f"(c[1]), "+f"(c[2]), "+f"(c[3])
        : "r"(a[0]), "r"(a[1]), "r"(a[2]), "r"(a[3]), "r"(b0), "r"(b1));
}

// ---------------------------------------------------------------------------
// router bias constants
// ---------------------------------------------------------------------------
__global__ void rconst_kernel(const float* __restrict__ Wr,
                              const float* __restrict__ loop_table,
                              const int* __restrict__ loop_idx) {
    __shared__ float red[256][NEXP];
    int li = loop_idx[0];
    float acc[NEXP];
#pragma unroll
    for (int e = 0; e < NEXP; e++) acc[e] = 0.f;
    for (int d = threadIdx.x; d < DIMD; d += 256) {
        float lv = loop_table[(size_t)li * DIMD + d];
        const float* wr = Wr + (size_t)(DIMD + d) * NEXP;
#pragma unroll
        for (int e = 0; e < NEXP; e++) acc[e] += lv * wr[e];
    }
#pragma unroll
    for (int e = 0; e < NEXP; e++) red[threadIdx.x][e] = acc[e];
    __syncthreads();
    if (threadIdx.x < NEXP) {
        float s = 0.f;
        for (int i = 0; i < 256; i++) s += red[i][threadIdx.x];
        g_rconst[threadIdx.x] = s;
    }
}

// ---------------------------------------------------------------------------
// router: one warp per token, stable top-2
// ---------------------------------------------------------------------------
__global__ void router_kernel(const float* __restrict__ x,
                              const float* __restrict__ Wr) {
    int warp = threadIdx.x >> 5, lane = threadIdx.x & 31;
    int n = blockIdx.x * 8 + warp;
    if (n >= NTOK) return;
    const float* xr = x + (size_t)n * DIMD;
    float acc[NEXP];
#pragma unroll
    for (int e = 0; e < NEXP; e++) acc[e] = 0.f;
    for (int d = lane; d < DIMD; d += 32) {
        float xv = xr[d];
        const float* wr = Wr + (size_t)d * NEXP;
#pragma unroll
        for (int e = 0; e < NEXP; e++) acc[e] += xv * wr[e];
    }
#pragma unroll
    for (int e = 0; e < NEXP; e++)
#pragma unroll
        for (int off = 16; off > 0; off >>= 1)
            acc[e] += __shfl_down_sync(0xffffffffu, acc[e], off);
    if (lane == 0) {
        float p[NEXP];
#pragma unroll
        for (int e = 0; e < NEXP; e++)
            p[e] = 1.f / (1.f + expf(-(acc[e] + g_rconst[e])));
        float b1 = -1.f; int i1 = 0;
#pragma unroll
        for (int e = 0; e < NEXP; e++) if (p[e] > b1) { b1 = p[e]; i1 = e; }
        float b2 = -1.f; int i2 = 0;
#pragma unroll
        for (int e = 0; e < NEXP; e++)
            if (e != i1 && p[e] > b2) { b2 = p[e]; i2 = e; }
        g_expert_of[2 * n]     = i1;  g_wslot[2 * n]     = b1;
        g_expert_of[2 * n + 1] = i2;  g_wslot[2 * n + 1] = b2;
    }
}

// ---------------------------------------------------------------------------
// dispatch: ordered per-expert slot lists
// ---------------------------------------------------------------------------
__global__ void dispatch_kernel() {
    int e = blockIdx.x;
    __shared__ int warp_tot[8];
    __shared__ int warp_off[8];
    __shared__ int s_base;
    if (threadIdx.x == 0) s_base = 0;
    __syncthreads();
    int lane = threadIdx.x & 31, w = threadIdx.x >> 5;
    for (int s0 = 0; s0 < SLOTS; s0 += 256) {
        int s = s0 + threadIdx.x;
        bool f = (g_expert_of[s] == e);
        unsigned bal = __ballot_sync(0xffffffffu, f);
        if (lane == 0) warp_tot[w] = __popc(bal);
        __syncthreads();
        if (threadIdx.x == 0) {
            int a = s_base;
            for (int i = 0; i < 8; i++) { warp_off[i] = a; a += warp_tot[i]; }
            s_base = a;
        }
        __syncthreads();
        if (f) {
            int pos = warp_off[w] + __popc(bal & ((1u << lane) - 1u));
            g_list[e * CAP + pos] = s;
        }
        __syncthreads();
    }
    if (threadIdx.x == 0) g_count[e] = s_base;
}

// ---------------------------------------------------------------------------
// x -> split bf16 hi/lo
// ---------------------------------------------------------------------------
__global__ void convert_x_kernel(const float* __restrict__ x) {
    size_t i = (size_t)blockIdx.x * 256 + threadIdx.x;  // float4 idx
    float4 v = ((const float4*)x)[i];
    __nv_bfloat16 h0 = __float2bfloat16(v.x), h1 = __float2bfloat16(v.y);
    __nv_bfloat16 h2 = __float2bfloat16(v.z), h3 = __float2bfloat16(v.w);
    __nv_bfloat162* HI = (__nv_bfloat162*)g_Xhi;
    __nv_bfloat162* LO = (__nv_bfloat162*)g_Xlo;
    HI[2 * i]     = __nv_bfloat162(h0, h1);
    HI[2 * i + 1] = __nv_bfloat162(h2, h3);
    LO[2 * i]     = __nv_bfloat162(__float2bfloat16(v.x - __bfloat162float(h0)),
                                   __float2bfloat16(v.y - __bfloat162float(h1)));
    LO[2 * i + 1] = __nv_bfloat162(__float2bfloat16(v.z - __bfloat162float(h2)),
                                   __float2bfloat16(v.w - __bfloat162float(h3)));
}

// ---------------------------------------------------------------------------
// weight transpose + split: dst[n][k] = src[k][n], 1024x1024 per matrix
// ---------------------------------------------------------------------------
__global__ void transpose_split_kernel(const float* __restrict__ src,
                                       __nv_bfloat16* __restrict__ dhi,
                                       __nv_bfloat16* __restrict__ dlo) {
    __shared__ float tile[32][33];
    size_t mbase = (size_t)blockIdx.z << 20;
    const float* S = src + mbase;
    int tx = threadIdx.x & 31, ty = threadIdx.x >> 5;
    int k0 = blockIdx.y * 32, n0 = blockIdx.x * 32;
#pragma unroll
    for (int i = 0; i < 4; i++)
        tile[ty + 8 * i][tx] = S[(size_t)(k0 + ty + 8 * i) * 1024 + n0 + tx];
    __syncthreads();
#pragma unroll
    for (int i = 0; i < 4; i++) {
        float v = tile[tx][ty + 8 * i];
        __nv_bfloat16 h = __float2bfloat16(v);
        size_t o = mbase + (size_t)(n0 + ty + 8 * i) * 1024 + k0 + tx;
        dhi[o] = h;
        dlo[o] = __float2bfloat16(v - __bfloat162float(h));
    }
}

// ---------------------------------------------------------------------------
// HMMA grouped GEMM: C[slot, n0:n0+128] = (A[arow] @ B_e^T) * w
// A: bf16 hi/lo [rows][1024]; B: bf16 hi/lo [e][1024(n)][1024(k)]
// Tile 128x128, BK=64, 8 warps (2M x 4N), warp tile 64x32, double-buffered
// cp.async, XOR-swizzled smem, 3 MMA terms per fragment (hi*hi,hi*lo,lo*hi).
//   amode: 0 arow=slot, 1 arow=slot>>1 (token), 2 arow=slot-SLOTS
// ---------------------------------------------------------------------------
#define GEMM_SMEM (1024 + 131072)
__global__ void __launch_bounds__(256, 1)
mma_gemm(const __nv_bfloat16* __restrict__ Ahi, const __nv_bfloat16* __restrict__ Alo,
         const __nv_bfloat16* __restrict__ BhiAll, const __nv_bfloat16* __restrict__ BloAll,
         float* __restrict__ C,
         const int* __restrict__ list, const int* __restrict__ counts, int fixed_count,
         int amode, int slot_base, const float* __restrict__ wslot) {
    int e = blockIdx.z;
    int cnt = list ? counts[e] : fixed_count;
    int m0 = blockIdx.y * 128;
    if (m0 >= cnt) return;
    int n0 = blockIdx.x * 128;
    const char* Bh = (const char*)(BhiAll + ((size_t)e << 20));
    const char* Bl = (const char*)(BloAll + ((size_t)e << 20));
    const char* Ah = (const char*)Ahi;
    const char* Al = (const char*)Alo;

    extern __shared__ __align__(128) char smem[];
    int*   slotArr = (int*)smem;
    float* wArr    = (float*)(smem + 512);
    uint32_t sb = smem_u32(smem);
    const uint32_t TB = sb + 1024;   // tile base

    int tid = threadIdx.x, lane = tid & 31, wid = tid >> 5;

    if (tid < 128) {
        int r = m0 + tid;
        int rc = (r < cnt) ? r : (cnt - 1);
        int slot = list ? list[e * CAP + rc] : (slot_base + rc);
        slotArr[tid] = slot;
        wArr[tid] = wslot ? wslot[slot] : 1.f;
    }
    __syncthreads();

    // ---- loader precompute: thread covers rows rb+32j, 16B k-chunk kc ----
    int rb = tid >> 3, kc = tid & 7;
    size_t aoff[4], boff[4];
    uint32_t dst[4];
#pragma unroll
    for (int j = 0; j < 4; j++) {
        int r = rb + 32 * j;
        int slot = slotArr[r];
        int arow = (amode == 1) ? (slot >> 1)
                 : (amode == 2) ? (slot - SLOTS) : slot;
        aoff[j] = ((size_t)arow * 1024 + kc * 8) * 2;          // bytes
        boff[j] = ((size_t)(n0 + r) * 1024 + kc * 8) * 2;      // bytes
        dst[j]  = (uint32_t)(r * 128 + ((kc ^ (r & 7)) * 16)); // swizzled
    }

    // stage layout: [stage][AH|AL|BH|BL] each 16KB
#define ST(stage, sub) (TB + (stage) * 65536u + (sub) * 16384u)

#define LOAD_STAGE(kb, stg) do {                                     \
    _Pragma("unroll")                                                \
    for (int j = 0; j < 4; j++) {                                    \
        cp16(ST(stg,0) + dst[j], Ah + aoff[j] + (kb));               \
        cp16(ST(stg,1) + dst[j], Al + aoff[j] + (kb));               \
        cp16(ST(stg,2) + dst[j], Bh + boff[j] + (kb));               \
        cp16(ST(stg,3) + dst[j], Bl + boff[j] + (kb));               \
    }                                                                \
    cp_commit(); } while (0)

    float acc[4][4][4];
#pragma unroll
    for (int i = 0; i < 4; i++)
#pragma unroll
        for (int j = 0; j < 4; j++)
#pragma unroll
            for (int q = 0; q < 4; q++) acc[i][j][q] = 0.f;

    int warpM = (wid & 1) * 64;
    int warpN = (wid >> 1) * 32;
    // ldmatrix lane geometry
    int a_r = (lane & 7) + 8 * ((lane >> 3) & 1);   // A: row within 16
    int a_c = (lane >> 4) & 1;                      // A: extra k-chunk
    int b_r = (lane & 7) + 8 * ((lane >> 4) & 1);   // B: n within 16
    int b_c = (lane >> 3) & 1;                      // B: extra k-chunk

    LOAD_STAGE(0, 0);

#pragma unroll 1
    for (int s = 0; s < 16; s++) {
        uint32_t stg = s & 1;
        if (s < 15) {
            LOAD_STAGE((size_t)(s + 1) * 128, (s + 1) & 1);
            CP_WAIT(1);
        } else {
            CP_WAIT(0);
        }
        __syncthreads();

#pragma unroll
        for (int kk = 0; kk < 4; kk++) {
            uint32_t a_hi[4][4], a_lo[4][4], b_hi[2][4], b_lo[2][4];
            int ac = 2 * kk + a_c;
            int bc = 2 * kk + b_c;
#pragma unroll
            for (int fm = 0; fm < 4; fm++) {
                int r = warpM + fm * 16 + a_r;
                uint32_t off = (uint32_t)(r * 128 + ((ac ^ (r & 7)) * 16));
                ldsm4(a_hi[fm], ST(stg, 0) + off);
                ldsm4(a_lo[fm], ST(stg, 1) + off);
            }
#pragma unroll
            for (int fb = 0; fb < 2; fb++) {
                int n = warpN + fb * 16 + b_r;
                uint32_t off = (uint32_t)(n * 128 + ((bc ^ (n & 7)) * 16));
                ldsm4(b_hi[fb], ST(stg, 2) + off);
                ldsm4(b_lo[fb], ST(stg, 3) + off);
            }
#pragma unroll
            for (int fm = 0; fm < 4; fm++)
#pragma unroll
                for (int fn = 0; fn < 4; fn++) {
                    int fb = fn >> 1, sel = (fn & 1) * 2;
                    mma16816(acc[fm][fn], a_hi[fm], b_hi[fb][sel], b_hi[fb][sel + 1]);
                    mma16816(acc[fm][fn], a_hi[fm], b_lo[fb][sel], b_lo[fb][sel + 1]);
                    mma16816(acc[fm][fn], a_lo[fm], b_hi[fb][sel], b_hi[fb][sel + 1]);
                }
        }
        __syncthreads();
    }

    // ---- epilogue: scatter scaled rows ----
#pragma unroll
    for (int fm = 0; fm < 4; fm++) {
        int rloc0 = warpM + fm * 16 + (lane >> 2);
        int rloc1 = rloc0 + 8;
        bool v0 = (m0 + rloc0) < cnt, v1 = (m0 + rloc1) < cnt;
        int s0 = slotArr[rloc0], s1 = slotArr[rloc1];
        float w0 = wArr[rloc0], w1 = wArr[rloc1];
        float* c0p = C + (size_t)s0 * 1024 + n0 + (lane & 3) * 2;
        float* c1p = C + (size_t)s1 * 1024 + n0 + (lane & 3) * 2;
#pragma unroll
        for (int fn = 0; fn < 4; fn++) {
            int coff = warpN + fn * 8;
            if (v0) *(float2*)(c0p + coff) =
                make_float2(acc[fm][fn][0] * w0, acc[fm][fn][1] * w0);
            if (v1) *(float2*)(c1p + coff) =
                make_float2(acc[fm][fn][2] * w1, acc[fm][fn][3] * w1);
        }
    }
#undef LOAD_STAGE
#undef ST
}

// ---------------------------------------------------------------------------
// h = silu(g)*u -> split bf16
// ---------------------------------------------------------------------------
__global__ void silumul_kernel() {
    size_t i = (size_t)blockIdx.x * 256 + threadIdx.x;  // float4 idx
    float4 g = ((const float4*)g_gbuf)[i];
    float4 u = ((const float4*)g_ubuf)[i];
    float h0 = g.x / (1.f + expf(-g.x)) * u.x;
    float h1 = g.y / (1.f + expf(-g.y)) * u.y;
    float h2 = g.z / (1.f + expf(-g.z)) * u.z;
    float h3 = g.w / (1.f + expf(-g.w)) * u.w;
    __nv_bfloat16 a0 = __float2bfloat16(h0), a1 = __float2bfloat16(h1);
    __nv_bfloat16 a2 = __float2bfloat16(h2), a3 = __float2bfloat16(h3);
    __nv_bfloat162* HI = (__nv_bfloat162*)g_Hhi;
    __nv_bfloat162* LO = (__nv_bfloat162*)g_Hlo;
    HI[2 * i]     = __nv_bfloat162(a0, a1);
    HI[2 * i + 1] = __nv_bfloat162(a2, a3);
    LO[2 * i]     = __nv_bfloat162(__float2bfloat16(h0 - __bfloat162float(a0)),
                                   __float2bfloat16(h1 - __bfloat162float(a1)));
    LO[2 * i + 1] = __nv_bfloat162(__float2bfloat16(h2 - __bfloat162float(a2)),
                                   __float2bfloat16(h3 - __bfloat162float(a3)));
}

// ---------------------------------------------------------------------------
// out[n] = shared + routed0 + routed1
// ---------------------------------------------------------------------------
__global__ void final_kernel(float* __restrict__ out) {
    size_t i = (size_t)blockIdx.x * 256 + threadIdx.x;  // float4 idx
    size_t n = i / (DIMD / 4);
    size_t c = i % (DIMD / 4);
    const float4* ysh = (const float4*)(g_ybuf + (size_t)(SLOTS + n) * DIMD);
    const float4* y0  = (const float4*)(g_ybuf + (size_t)(2 * n) * DIMD);
    const float4* y1  = (const float4*)(g_ybuf + (size_t)(2 * n + 1) * DIMD);
    float4 a = ysh[c], b = y0[c], d = y1[c];
    ((float4*)out)[i] = make_float4(a.x + b.x + d.x, a.y + b.y + d.y,
                                    a.z + b.z + d.z, a.w + b.w + d.w);
}

// ---------------------------------------------------------------------------
extern "C" void kernel_launch(void* const* d_in, const int* in_sizes, int n_in,
                              void* d_out, int out_size) {
    const float* x  = (const float*)d_in[0];
    const float* sg = (const float*)d_in[1];
    const float* su = (const float*)d_in[2];
    const float* sd = (const float*)d_in[3];
    const float* Wg = (const float*)d_in[4];
    const float* Wu = (const float*)d_in[5];
    const float* Wd = (const float*)d_in[6];
    const float* Wr = (const float*)d_in[7];
    const float* lt = (const float*)d_in[8];
    const int*   li = (const int*)d_in[9];
    float* out = (float*)d_out;

    cudaFuncSetAttribute(mma_gemm, cudaFuncAttributeMaxDynamicSharedMemorySize,
                         GEMM_SMEM);

    float *gbuf, *ubuf, *ybuf, *ws;
    int *list, *count;
    __nv_bfloat16 *Xhi, *Xlo, *Hhi, *Hlo;
    __nv_bfloat16 *WgThi, *WgTlo, *WuThi, *WuTlo, *WdThi, *WdTlo;
    __nv_bfloat16 *sgThi, *sgTlo, *suThi, *suTlo, *sdThi, *sdTlo;
    cudaGetSymbolAddress((void**)&gbuf,  g_gbuf);
    cudaGetSymbolAddress((void**)&ubuf,  g_ubuf);
    cudaGetSymbolAddress((void**)&ybuf,  g_ybuf);
    cudaGetSymbolAddress((void**)&ws,    g_wslot);
    cudaGetSymbolAddress((void**)&list,  g_list);
    cudaGetSymbolAddress((void**)&count, g_count);
    cudaGetSymbolAddress((void**)&Xhi,   g_Xhi);
    cudaGetSymbolAddress((void**)&Xlo,   g_Xlo);
    cudaGetSymbolAddress((void**)&Hhi,   g_Hhi);
    cudaGetSymbolAddress((void**)&Hlo,   g_Hlo);
    cudaGetSymbolAddress((void**)&WgThi, g_WgThi);
    cudaGetSymbolAddress((void**)&WgTlo, g_WgTlo);
    cudaGetSymbolAddress((void**)&WuThi, g_WuThi);
    cudaGetSymbolAddress((void**)&WuTlo, g_WuTlo);
    cudaGetSymbolAddress((void**)&WdThi, g_WdThi);
    cudaGetSymbolAddress((void**)&WdTlo, g_WdTlo);
    cudaGetSymbolAddress((void**)&sgThi, g_sgThi);
    cudaGetSymbolAddress((void**)&sgTlo, g_sgTlo);
    cudaGetSymbolAddress((void**)&suThi, g_suThi);
    cudaGetSymbolAddress((void**)&suTlo, g_suTlo);
    cudaGetSymbolAddress((void**)&sdThi, g_sdThi);
    cudaGetSymbolAddress((void**)&sdTlo, g_sdTlo);

    // routing
    rconst_kernel<<<1, 256>>>(Wr, lt, li);
    router_kernel<<<NTOK / 8, 256>>>(x, Wr);
    dispatch_kernel<<<NEXP, 256>>>();

    // precision-split conversions
    convert_x_kernel<<<(NTOK * 1024 / 4) / 256, 256>>>(x);
    transpose_split_kernel<<<dim3(32, 32, NEXP), 256>>>(Wg, WgThi, WgTlo);
    transpose_split_kernel<<<dim3(32, 32, NEXP), 256>>>(Wu, WuThi, WuTlo);
    transpose_split_kernel<<<dim3(32, 32, NEXP), 256>>>(Wd, WdThi, WdTlo);
    transpose_split_kernel<<<dim3(32, 32, 1), 256>>>(sg, sgThi, sgTlo);
    transpose_split_kernel<<<dim3(32, 32, 1), 256>>>(su, suThi, suTlo);
    transpose_split_kernel<<<dim3(32, 32, 1), 256>>>(sd, sdThi, sdTlo);

    dim3 gr(8, CAP / 128, NEXP);   // routed: 8 N-tiles, 64 M-tiles, 8 experts
    dim3 gs(8, NTOK / 128, 1);     // shared: 32 M-tiles

    // gate
    mma_gemm<<<gr, 256, GEMM_SMEM>>>(Xhi, Xlo, WgThi, WgTlo, gbuf,
                                     list, count, 0, 1, 0, nullptr);
    mma_gemm<<<gs, 256, GEMM_SMEM>>>(Xhi, Xlo, sgThi, sgTlo, gbuf,
                                     nullptr, nullptr, NTOK, 2, SLOTS, nullptr);
    // up
    mma_gemm<<<gr, 256, GEMM_SMEM>>>(Xhi, Xlo, WuThi, WuTlo, ubuf,
                                     list, count, 0, 1, 0, nullptr);
    mma_gemm<<<gs, 256, GEMM_SMEM>>>(Xhi, Xlo, suThi, suTlo, ubuf,
                                     nullptr, nullptr, NTOK, 2, SLOTS, nullptr);
    // h = silu(g)*u  (split)
    silumul_kernel<<<(int)(((size_t)TOT * 1024 / 4) / 256), 256>>>();
    // down (routed scaled by routing weight)
    mma_gemm<<<gr, 256, GEMM_SMEM>>>(Hhi, Hlo, WdThi, WdTlo, ybuf,
                                     list, count, 0, 0, 0, ws);
    mma_gemm<<<gs, 256, GEMM_SMEM>>>(Hhi, Hlo, sdThi, sdTlo, ybuf,
                                     nullptr, nullptr, NTOK, 0, SLOTS, nullptr);
    // combine
    final_kernel<<<(NTOK * DIMD / 4) / 256, 256>>>(out);
}